// round 13
// baseline (speedup 1.0000x reference)
#include <cuda_runtime.h>

// Problem constants (fixed by setup_inputs)
#define B_    4
#define H_    64
#define W_    96
#define CH_   1152      // K*K*128
#define WCH_  (W_ * CH_)
#define C_    128
#define S_    6
#define IMW_  1536.0f
#define IMH_  1024.0f

#define NB      64       // 4 batches x 16 y-cells
#define MAXROI  8192
#define NSM     148

__device__ int g_order[MAXROI];
__device__ unsigned char g_key[MAXROI];

// Pass 1: counting sort of ROI indices by (batch, y-cell). Within-bucket
// order is arbitrary (output is indexed by ROI id), so atomic scatter is fine.
__global__ void roi_sort_kernel(const float* __restrict__ rois, int nroi)
{
    __shared__ int hist[NB];
    __shared__ int offs[NB];
    const int tid = threadIdx.x;

    if (tid < NB) hist[tid] = 0;
    __syncthreads();

    for (int i = tid; i < nroi; i += blockDim.x) {
        const int   bb = ((int)rois[i * 5 + 0]) & 3;
        const float y1 = rois[i * 5 + 2];
        int yc = (int)(y1 * (16.0f / IMH_));
        yc = yc < 0 ? 0 : (yc > 15 ? 15 : yc);
        const int key = bb * 16 + yc;
        g_key[i] = (unsigned char)key;
        atomicAdd(&hist[key], 1);
    }
    __syncthreads();

    if (tid == 0) {
        int a = 0;
        #pragma unroll
        for (int k = 0; k < NB; ++k) { offs[k] = a; a += hist[k]; }
    }
    __syncthreads();

    for (int i = tid; i < nroi; i += blockDim.x) {
        const int pos = atomicAdd(&offs[g_key[i]], 1);
        g_order[pos] = i;
    }
}

// Pass 2: main kernel. SM = f(bid % 148) for classic launches, so remap
// rank = (bid % 148)*P + bid/148: each SM owns a CONTIGUOUS run of P sorted
// ROIs -> its 4 co-resident CTAs share one (batch,y) slab in L1, and
// successive CTAs on the SM continue that slab (L1 persists within launch).
__global__ __launch_bounds__(256, 4) void rroi_kernel(
    const float* __restrict__ fm,
    const float* __restrict__ rois,
    float* __restrict__ out,
    int nroi, int P, int use_order)
{
    const int bid  = blockIdx.x;
    const int rank = (bid % NSM) * P + bid / NSM;
    if (rank >= nroi) return;
    const int n = use_order ? g_order[rank] : rank;

    const int tid  = threadIdx.x;
    const int wz   = tid >> 5;
    const int lane = tid & 31;

    // raw (uncompacted) descriptor tables
    __shared__ float tyw0[18], tyw1[18], txw0[18];
    __shared__ int   tyr0[18], tyr1[18], txc0[18], txc1[18];
    __shared__ int   tyv[18], txv[18];
    // compacted lists
    __shared__ int   cYr0[18], cYr1[18], cYch[18];
    __shared__ float cYw0[18], cYw1[18];
    __shared__ int   cXc0[18], cXc1[18], cXch[18];
    __shared__ float cXw0[18];
    __shared__ int   sNy, sNx;
    // per-pair compact descriptors (padded)
    __shared__ __align__(16) int4  sDesc[352];
    __shared__ __align__(16) float part[8 * C_];

    // ROI params (broadcast loads)
    const float rb  = rois[n * 5 + 0];
    const float rx1 = rois[n * 5 + 1];
    const float ry1 = rois[n * 5 + 2];
    const float rx2 = rois[n * 5 + 3];
    const float ry2 = rois[n * 5 + 4];

    const int   b   = (int)rb;
    const float bx1 = rx1 / IMW_;
    const float by1 = ry1 / IMH_;
    const float bx2 = rx2 / IMW_;
    const float by2 = ry2 / IMH_;

    const float bin_w = (bx2 - bx1) / 3.0f;
    const float bin_h = by2 - by1 / 3.0f;      // reference bug, replicated

    // Phase 1: 18 y-descriptors (threads 0-17), 18 x-descriptors (threads 64-81)
    if (tid < 18) {
        const int d  = tid;
        const int ih = d / 6;
        const int sy = d - ih * 6;
        const float cy1 = by1 + (float)ih * bin_h;
        const float cy2 = by1 + (float)(ih + 1) * bin_h;
        const float ysv = cy1 * (float)(H_ - 1)
                        + (float)sy * ((cy2 - cy1) * (float)(H_ - 1) / (float)(S_ - 1));
        const int valid = (ysv >= 0.0f) && (ysv <= (float)(H_ - 1));
        const float y0f = floorf(ysv);
        const float ly  = ysv - y0f;
        int i0 = (int)y0f;
        i0 = i0 < 0 ? 0 : (i0 > H_ - 1 ? H_ - 1 : i0);
        int i1 = i0 + 1 > H_ - 1 ? H_ - 1 : i0 + 1;
        tyv[d]  = valid;
        tyr0[d] = i0 * WCH_;
        tyr1[d] = i1 * WCH_;
        tyw0[d] = 1.0f - ly;
        tyw1[d] = ly;
    } else if (tid >= 64 && tid < 82) {
        const int d  = tid - 64;
        const int iw = d / 6;
        const int sx = d - iw * 6;
        const float cx1 = bx1 + (float)iw * bin_w;
        const float cx2 = bx1 + (float)(iw + 1) * bin_h;   // reference bug, replicated
        const float xsv = cx1 * (float)(W_ - 1)
                        + (float)sx * ((cx2 - cx1) * (float)(W_ - 1) / (float)(S_ - 1));
        const int valid = (xsv >= 0.0f) && (xsv <= (float)(W_ - 1));
        const float x0f = floorf(xsv);
        const float lx  = xsv - x0f;
        int i0 = (int)x0f;
        i0 = i0 < 0 ? 0 : (i0 > W_ - 1 ? W_ - 1 : i0);
        int i1 = i0 + 1 > W_ - 1 ? W_ - 1 : i0 + 1;
        txv[d]  = valid;
        txc0[d] = i0 * CH_;
        txc1[d] = i1 * CH_;
        txw0[d] = 1.0f - lx;
    }
    __syncthreads();

    // Phase 2: compact valid descriptors (two threads in different warps)
    if (tid == 0) {
        int c = 0;
        #pragma unroll
        for (int d = 0; d < 18; ++d) {
            if (tyv[d]) {
                cYr0[c] = tyr0[d];
                cYr1[c] = tyr1[d];
                cYw0[c] = tyw0[d];
                cYw1[c] = tyw1[d];
                cYch[c] = (d / 6) * (3 * C_);   // ih*3*C
                ++c;
            }
        }
        sNy = c;
    } else if (tid == 32) {
        int c = 0;
        #pragma unroll
        for (int d = 0; d < 18; ++d) {
            if (txv[d]) {
                cXc0[c] = txc0[d];
                cXc1[c] = txc1[d];
                cXw0[c] = txw0[d];
                cXch[c] = (d / 6) * C_;         // iw*C
                ++c;
            }
        }
        sNx = c;
    }
    __syncthreads();

    const int ny = sNy, nx = sNx;
    const int total = ny * nx;
    const int totp  = (total + 15) & ~15;   // padded loop bound (mult of 16)

    // Phase 3: build compact descriptors; zero-pad [total, totp+16)
    for (int p = tid; p < totp + 16; p += 256) {
        int4 d;
        if (p < total) {
            const int yi = p / nx;
            const int xi = p - yi * nx;
            const int ox = cYr0[yi] + cXc0[xi] + cYch[yi] + cXch[xi];
            const int fl = ((cYr1[yi] != cYr0[yi]) ? 2 : 0)
                         | ((cXc1[xi] != cXc0[xi]) ? 1 : 0);
            d.x = ox | fl;                      // ox is a multiple of 128
            d.y = __float_as_int(cYw0[yi]);     // wy0
            d.z = __float_as_int(cYw1[yi]);     // wy1
            d.w = __float_as_int(cXw0[xi]);     // wx0
        } else {
            d = make_int4(0, 0, 0, 0);          // all-zero weights -> no contribution
        }
        sDesc[p] = d;
    }
    __syncthreads();

    // Main loop (unrolled x2, descriptor prefetch): 8 warps stride samples.
    const float* pb = fm + (size_t)b * (H_ * W_ * CH_) + lane * 4;

    float4 acc0 = make_float4(0.0f, 0.0f, 0.0f, 0.0f);
    float4 acc1 = make_float4(0.0f, 0.0f, 0.0f, 0.0f);

    int4 dA = sDesc[wz];
    int4 dB = sDesc[wz + 8];

    for (int p = wz; p < totp; p += 16) {
        // decode A
        const int oxA = dA.x & ~3;
        const int dyA = (dA.x & 2) ? WCH_ : 0;
        const int dxA = (dA.x & 1) ? CH_  : 0;
        const float wy0A = __int_as_float(dA.y);
        const float wy1A = __int_as_float(dA.z);
        const float wx0A = __int_as_float(dA.w);
        const float wx1A = 1.0f - wx0A;
        // decode B
        const int oxB = dB.x & ~3;
        const int dyB = (dB.x & 2) ? WCH_ : 0;
        const int dxB = (dB.x & 1) ? CH_  : 0;
        const float wy0B = __int_as_float(dB.y);
        const float wy1B = __int_as_float(dB.z);
        const float wx0B = __int_as_float(dB.w);
        const float wx1B = 1.0f - wx0B;

        // 8 independent LDG.128 in flight
        const float4 a00 = *(const float4*)(pb + oxA);
        const float4 a01 = *(const float4*)(pb + oxA + dxA);
        const float4 a10 = *(const float4*)(pb + oxA + dyA);
        const float4 a11 = *(const float4*)(pb + oxA + dyA + dxA);
        const float4 b00 = *(const float4*)(pb + oxB);
        const float4 b01 = *(const float4*)(pb + oxB + dxB);
        const float4 b10 = *(const float4*)(pb + oxB + dyB);
        const float4 b11 = *(const float4*)(pb + oxB + dyB + dxB);

        // prefetch next iteration's descriptors (LDS overlaps LDG latency)
        const int4 nA = sDesc[p + 16];
        const int4 nB = sDesc[p + 24];

        const float w00A = wy0A * wx0A, w01A = wy0A * wx1A;
        const float w10A = wy1A * wx0A, w11A = wy1A * wx1A;
        const float w00B = wy0B * wx0B, w01B = wy0B * wx1B;
        const float w10B = wy1B * wx0B, w11B = wy1B * wx1B;

        acc0.x += w00A * a00.x + w01A * a01.x + w10A * a10.x + w11A * a11.x;
        acc0.y += w00A * a00.y + w01A * a01.y + w10A * a10.y + w11A * a11.y;
        acc0.z += w00A * a00.z + w01A * a01.z + w10A * a10.z + w11A * a11.z;
        acc0.w += w00A * a00.w + w01A * a01.w + w10A * a10.w + w11A * a11.w;

        acc1.x += w00B * b00.x + w01B * b01.x + w10B * b10.x + w11B * b11.x;
        acc1.y += w00B * b00.y + w01B * b01.y + w10B * b10.y + w11B * b11.y;
        acc1.z += w00B * b00.z + w01B * b01.z + w10B * b10.z + w11B * b11.z;
        acc1.w += w00B * b00.w + w01B * b01.w + w10B * b10.w + w11B * b11.w;

        dA = nA;
        dB = nB;
    }

    acc0.x += acc1.x; acc0.y += acc1.y; acc0.z += acc1.z; acc0.w += acc1.w;

    // Deterministic cross-warp reduction
    ((float4*)part)[wz * 32 + lane] = acc0;
    __syncthreads();

    if (tid < C_) {
        float ssum = 0.0f;
        #pragma unroll
        for (int w = 0; w < 8; ++w) ssum += part[w * C_ + tid];
        out[n * C_ + tid] = ssum * (1.0f / 324.0f);
    }
}

extern "C" void kernel_launch(void* const* d_in, const int* in_sizes, int n_in,
                              void* d_out, int out_size) {
    const float* fm   = (const float*)d_in[0];
    const float* rois = (const float*)d_in[1];
    float* out        = (float*)d_out;
    const int nroi    = in_sizes[1] / 5;

    const int use_order = (nroi <= MAXROI) ? 1 : 0;
    if (use_order) {
        roi_sort_kernel<<<1, 1024>>>(rois, nroi);
    }
    const int P    = (nroi + NSM - 1) / NSM;
    const int grid = NSM * P;
    rroi_kernel<<<grid, 256>>>(fm, rois, out, nroi, P, use_order);
}

// round 14
// speedup vs baseline: 1.0882x; 1.0882x over previous
#include <cuda_runtime.h>

// Problem constants (fixed by setup_inputs)
#define B_    4
#define H_    64
#define W_    96
#define CH_   1152      // K*K*128
#define WCH_  (W_ * CH_)
#define C_    128
#define S_    6
#define IMW_  1536.0f
#define IMH_  1024.0f

#define NB      128      // 4 batches x 8 y-cells x 4 x-cells
#define MAXROI  8192

__device__ int g_order[MAXROI];
__device__ unsigned char g_key[MAXROI];

// Pass 1: counting sort of ROI indices by (batch, y-cell, x-cell).
// Within-bucket order is arbitrary (output is indexed by ROI id, so the
// permutation does not affect results); atomicAdd scatter is fine.
__global__ void roi_sort_kernel(const float* __restrict__ rois, int nroi)
{
    __shared__ int hist[NB];
    __shared__ int offs[NB];
    const int tid = threadIdx.x;

    if (tid < NB) hist[tid] = 0;
    __syncthreads();

    for (int i = tid; i < nroi; i += blockDim.x) {
        const int   bb = ((int)rois[i * 5 + 0]) & 3;
        const float x1 = rois[i * 5 + 1];
        const float y1 = rois[i * 5 + 2];
        int yc = (int)(y1 * (8.0f / IMH_));
        yc = yc < 0 ? 0 : (yc > 7 ? 7 : yc);
        int xc = (int)(x1 * (4.0f / IMW_));
        xc = xc < 0 ? 0 : (xc > 3 ? 3 : xc);
        const int key = (bb << 5) | (yc << 2) | xc;
        g_key[i] = (unsigned char)key;
        atomicAdd(&hist[key], 1);
    }
    __syncthreads();

    if (tid == 0) {
        int a = 0;
        #pragma unroll
        for (int k = 0; k < NB; ++k) { offs[k] = a; a += hist[k]; }
    }
    __syncthreads();

    for (int i = tid; i < nroi; i += blockDim.x) {
        const int pos = atomicAdd(&offs[g_key[i]], 1);
        g_order[pos] = i;
    }
}

// Pass 2: main kernel, CTA bid processes ROI g_order[bid]. The concurrent
// wave (~600 adjacent bids) then works one compact (batch,y,x) slab -> L2
// locality. (R10 showed per-SM remapping destroys this; keep rank = bid.)
__global__ __launch_bounds__(256, 4) void rroi_kernel(
    const float* __restrict__ fm,
    const float* __restrict__ rois,
    float* __restrict__ out,
    int nroi, int use_order)
{
    const int bid = blockIdx.x;
    if (bid >= nroi) return;
    const int n = use_order ? g_order[bid] : bid;

    const int tid  = threadIdx.x;
    const int wz   = tid >> 5;
    const int lane = tid & 31;

    // raw (uncompacted) descriptor tables
    __shared__ float tyw0[18], tyw1[18], txw0[18];
    __shared__ int   tyr0[18], tyr1[18], txc0[18], txc1[18];
    __shared__ int   tyv[18], txv[18];
    // compacted lists
    __shared__ int   cYr0[18], cYr1[18], cYch[18];
    __shared__ float cYw0[18], cYw1[18];
    __shared__ int   cXc0[18], cXc1[18], cXch[18];
    __shared__ float cXw0[18];
    __shared__ int   sNy, sNx;
    // per-pair compact descriptors (padded)
    __shared__ __align__(16) int4  sDesc[352];
    __shared__ __align__(16) float part[8 * C_];

    // ROI params (broadcast loads)
    const float rb  = rois[n * 5 + 0];
    const float rx1 = rois[n * 5 + 1];
    const float ry1 = rois[n * 5 + 2];
    const float rx2 = rois[n * 5 + 3];
    const float ry2 = rois[n * 5 + 4];

    const int   b   = (int)rb;
    const float bx1 = rx1 / IMW_;
    const float by1 = ry1 / IMH_;
    const float bx2 = rx2 / IMW_;
    const float by2 = ry2 / IMH_;

    const float bin_w = (bx2 - bx1) / 3.0f;
    const float bin_h = by2 - by1 / 3.0f;      // reference bug, replicated

    // Phase 1: 18 y-descriptors (threads 0-17), 18 x-descriptors (threads 64-81)
    if (tid < 18) {
        const int d  = tid;
        const int ih = d / 6;
        const int sy = d - ih * 6;
        const float cy1 = by1 + (float)ih * bin_h;
        const float cy2 = by1 + (float)(ih + 1) * bin_h;
        const float ysv = cy1 * (float)(H_ - 1)
                        + (float)sy * ((cy2 - cy1) * (float)(H_ - 1) / (float)(S_ - 1));
        const int valid = (ysv >= 0.0f) && (ysv <= (float)(H_ - 1));
        const float y0f = floorf(ysv);
        const float ly  = ysv - y0f;
        int i0 = (int)y0f;
        i0 = i0 < 0 ? 0 : (i0 > H_ - 1 ? H_ - 1 : i0);
        int i1 = i0 + 1 > H_ - 1 ? H_ - 1 : i0 + 1;
        tyv[d]  = valid;
        tyr0[d] = i0 * WCH_;
        tyr1[d] = i1 * WCH_;
        tyw0[d] = 1.0f - ly;
        tyw1[d] = ly;
    } else if (tid >= 64 && tid < 82) {
        const int d  = tid - 64;
        const int iw = d / 6;
        const int sx = d - iw * 6;
        const float cx1 = bx1 + (float)iw * bin_w;
        const float cx2 = bx1 + (float)(iw + 1) * bin_h;   // reference bug, replicated
        const float xsv = cx1 * (float)(W_ - 1)
                        + (float)sx * ((cx2 - cx1) * (float)(W_ - 1) / (float)(S_ - 1));
        const int valid = (xsv >= 0.0f) && (xsv <= (float)(W_ - 1));
        const float x0f = floorf(xsv);
        const float lx  = xsv - x0f;
        int i0 = (int)x0f;
        i0 = i0 < 0 ? 0 : (i0 > W_ - 1 ? W_ - 1 : i0);
        int i1 = i0 + 1 > W_ - 1 ? W_ - 1 : i0 + 1;
        txv[d]  = valid;
        txc0[d] = i0 * CH_;
        txc1[d] = i1 * CH_;
        txw0[d] = 1.0f - lx;
    }
    __syncthreads();

    // Phase 2: compact valid descriptors (two threads in different warps)
    if (tid == 0) {
        int c = 0;
        #pragma unroll
        for (int d = 0; d < 18; ++d) {
            if (tyv[d]) {
                cYr0[c] = tyr0[d];
                cYr1[c] = tyr1[d];
                cYw0[c] = tyw0[d];
                cYw1[c] = tyw1[d];
                cYch[c] = (d / 6) * (3 * C_);   // ih*3*C
                ++c;
            }
        }
        sNy = c;
    } else if (tid == 32) {
        int c = 0;
        #pragma unroll
        for (int d = 0; d < 18; ++d) {
            if (txv[d]) {
                cXc0[c] = txc0[d];
                cXc1[c] = txc1[d];
                cXw0[c] = txw0[d];
                cXch[c] = (d / 6) * C_;         // iw*C
                ++c;
            }
        }
        sNx = c;
    }
    __syncthreads();

    const int ny = sNy, nx = sNx;
    const int total = ny * nx;
    const int totp  = (total + 15) & ~15;   // padded loop bound (mult of 16)

    // Phase 3: build compact descriptors; zero-pad [total, totp+16)
    for (int p = tid; p < totp + 16; p += 256) {
        int4 d;
        if (p < total) {
            const int yi = p / nx;
            const int xi = p - yi * nx;
            const int ox = cYr0[yi] + cXc0[xi] + cYch[yi] + cXch[xi];
            const int fl = ((cYr1[yi] != cYr0[yi]) ? 2 : 0)
                         | ((cXc1[xi] != cXc0[xi]) ? 1 : 0);
            d.x = ox | fl;                      // ox is a multiple of 128
            d.y = __float_as_int(cYw0[yi]);     // wy0
            d.z = __float_as_int(cYw1[yi]);     // wy1
            d.w = __float_as_int(cXw0[xi]);     // wx0
        } else {
            d = make_int4(0, 0, 0, 0);          // all-zero weights -> no contribution
        }
        sDesc[p] = d;
    }
    __syncthreads();

    // Main loop (unrolled x2, descriptor prefetch): 8 warps stride samples.
    const float* pb = fm + (size_t)b * (H_ * W_ * CH_) + lane * 4;

    float4 acc0 = make_float4(0.0f, 0.0f, 0.0f, 0.0f);
    float4 acc1 = make_float4(0.0f, 0.0f, 0.0f, 0.0f);

    int4 dA = sDesc[wz];
    int4 dB = sDesc[wz + 8];

    for (int p = wz; p < totp; p += 16) {
        // decode A
        const int oxA = dA.x & ~3;
        const int dyA = (dA.x & 2) ? WCH_ : 0;
        const int dxA = (dA.x & 1) ? CH_  : 0;
        const float wy0A = __int_as_float(dA.y);
        const float wy1A = __int_as_float(dA.z);
        const float wx0A = __int_as_float(dA.w);
        const float wx1A = 1.0f - wx0A;
        // decode B
        const int oxB = dB.x & ~3;
        const int dyB = (dB.x & 2) ? WCH_ : 0;
        const int dxB = (dB.x & 1) ? CH_  : 0;
        const float wy0B = __int_as_float(dB.y);
        const float wy1B = __int_as_float(dB.z);
        const float wx0B = __int_as_float(dB.w);
        const float wx1B = 1.0f - wx0B;

        // 8 independent LDG.128 in flight
        const float4 a00 = *(const float4*)(pb + oxA);
        const float4 a01 = *(const float4*)(pb + oxA + dxA);
        const float4 a10 = *(const float4*)(pb + oxA + dyA);
        const float4 a11 = *(const float4*)(pb + oxA + dyA + dxA);
        const float4 b00 = *(const float4*)(pb + oxB);
        const float4 b01 = *(const float4*)(pb + oxB + dxB);
        const float4 b10 = *(const float4*)(pb + oxB + dyB);
        const float4 b11 = *(const float4*)(pb + oxB + dyB + dxB);

        // prefetch next iteration's descriptors (LDS overlaps LDG latency)
        const int4 nA = sDesc[p + 16];
        const int4 nB = sDesc[p + 24];

        const float w00A = wy0A * wx0A, w01A = wy0A * wx1A;
        const float w10A = wy1A * wx0A, w11A = wy1A * wx1A;
        const float w00B = wy0B * wx0B, w01B = wy0B * wx1B;
        const float w10B = wy1B * wx0B, w11B = wy1B * wx1B;

        acc0.x += w00A * a00.x + w01A * a01.x + w10A * a10.x + w11A * a11.x;
        acc0.y += w00A * a00.y + w01A * a01.y + w10A * a10.y + w11A * a11.y;
        acc0.z += w00A * a00.z + w01A * a01.z + w10A * a10.z + w11A * a11.z;
        acc0.w += w00A * a00.w + w01A * a01.w + w10A * a10.w + w11A * a11.w;

        acc1.x += w00B * b00.x + w01B * b01.x + w10B * b10.x + w11B * b11.x;
        acc1.y += w00B * b00.y + w01B * b01.y + w10B * b10.y + w11B * b11.y;
        acc1.z += w00B * b00.z + w01B * b01.z + w10B * b10.z + w11B * b11.z;
        acc1.w += w00B * b00.w + w01B * b01.w + w10B * b10.w + w11B * b11.w;

        dA = nA;
        dB = nB;
    }

    acc0.x += acc1.x; acc0.y += acc1.y; acc0.z += acc1.z; acc0.w += acc1.w;

    // Deterministic cross-warp reduction
    ((float4*)part)[wz * 32 + lane] = acc0;
    __syncthreads();

    if (tid < C_) {
        float ssum = 0.0f;
        #pragma unroll
        for (int w = 0; w < 8; ++w) ssum += part[w * C_ + tid];
        out[n * C_ + tid] = ssum * (1.0f / 324.0f);
    }
}

extern "C" void kernel_launch(void* const* d_in, const int* in_sizes, int n_in,
                              void* d_out, int out_size) {
    const float* fm   = (const float*)d_in[0];
    const float* rois = (const float*)d_in[1];
    float* out        = (float*)d_out;
    const int nroi    = in_sizes[1] / 5;

    const int use_order = (nroi <= MAXROI) ? 1 : 0;
    if (use_order) {
        roi_sort_kernel<<<1, 1024>>>(rois, nroi);
    }
    rroi_kernel<<<nroi, 256>>>(fm, rois, out, nroi, use_order);
}